// round 10
// baseline (speedup 1.0000x reference)
#include <cuda_runtime.h>
#include <cuda_fp16.h>
#include <math.h>

#define NN 20000
#define EE 640000

// ---------------- scratch (static device globals; no allocation) ----------------
__device__ float  g_q[NN * 128];
__device__ __half g_xh[NN * 128];         // fp16 copy of x for tensor-core GEMM
__device__ __half g_kvp[NN * 384];        // packed per-node record: k[128] | v[128] | psi[128]
__device__ float  g_hcat[NN * 256];
__device__ int    g_row[EE];
__device__ int    g_col[EE];
__device__ int    g_scol[EE];
__device__ int    g_counts[NN];
__device__ int    g_off[NN + 1];
__device__ int    g_cur[NN];
__device__ int    g_is64;

// ---------------- ptx helpers ----------------
__device__ __forceinline__ unsigned smem_u32(const void* p) {
    return (unsigned)__cvta_generic_to_shared(p);
}
__device__ __forceinline__ void ldsm_x4(unsigned& r0, unsigned& r1, unsigned& r2, unsigned& r3,
                                        unsigned addr) {
    asm volatile("ldmatrix.sync.aligned.m8n8.x4.shared.b16 {%0,%1,%2,%3}, [%4];"
                 : "=r"(r0), "=r"(r1), "=r"(r2), "=r"(r3) : "r"(addr));
}
__device__ __forceinline__ void ldsm_x4_t(unsigned& r0, unsigned& r1, unsigned& r2, unsigned& r3,
                                          unsigned addr) {
    asm volatile("ldmatrix.sync.aligned.m8n8.x4.trans.shared.b16 {%0,%1,%2,%3}, [%4];"
                 : "=r"(r0), "=r"(r1), "=r"(r2), "=r"(r3) : "r"(addr));
}
__device__ __forceinline__ void mma16816(float* d, unsigned a0, unsigned a1, unsigned a2,
                                         unsigned a3, unsigned b0, unsigned b1) {
    asm volatile(
        "mma.sync.aligned.m16n8k16.row.col.f32.f16.f16.f32 "
        "{%0,%1,%2,%3}, {%4,%5,%6,%7}, {%8,%9}, {%0,%1,%2,%3};"
        : "+f"(d[0]), "+f"(d[1]), "+f"(d[2]), "+f"(d[3])
        : "r"(a0), "r"(a1), "r"(a2), "r"(a3), "r"(b0), "r"(b1));
}

// ---------------- fused: zero counts + edge_index dtype detection ----------------
__global__ void detect_zero_kernel(const int* __restrict__ p) {
    int i = blockIdx.x * 1024 + threadIdx.x;
    if (i < NN) g_counts[i] = 0;
    if (blockIdx.x == 0 && threadIdx.x < 32) {
        int l = threadIdx.x;
        int bad = (p[2 * l + 1] != 0);
        unsigned m = __ballot_sync(0xffffffffu, bad);
        if (l == 0) g_is64 = (m == 0u) ? 1 : 0;
    }
}

// ---------------- x -> fp16 ----------------
__global__ void x2h_kernel(const float* __restrict__ X) {
    int i = blockIdx.x * 256 + threadIdx.x;     // 320000 threads, 8 floats each
    float4 v0 = ((const float4*)X)[i * 2];
    float4 v1 = ((const float4*)X)[i * 2 + 1];
    __half2 h0 = __floats2half2_rn(v0.x, v0.y);
    __half2 h1 = __floats2half2_rn(v0.z, v0.w);
    __half2 h2 = __floats2half2_rn(v1.x, v1.y);
    __half2 h3 = __floats2half2_rn(v1.z, v1.w);
    uint4 o;
    o.x = *(unsigned*)&h0; o.y = *(unsigned*)&h1;
    o.z = *(unsigned*)&h2; o.w = *(unsigned*)&h3;
    *((uint4*)(g_xh + (size_t)i * 8)) = o;
}

// ---------------- fused decode + histogram ----------------
__global__ void decode_hist_kernel(const void* __restrict__ ei) {
    int e = blockIdx.x * 1024 + threadIdx.x;
    int r, c;
    if (g_is64) {
        const long long* q = (const long long*)ei;
        r = (int)q[e]; c = (int)q[EE + e];
    } else {
        const int* q = (const int*)ei;
        r = q[e]; c = q[EE + e];
    }
    g_row[e] = r;
    g_col[e] = c;
    atomicAdd(&g_counts[r], 1);
}

// ---------------- exclusive scan: chunked warp-shfl, coalesced ----------------
__global__ void scan_kernel() {
    __shared__ int wsums[32];
    const int t = threadIdx.x;
    const int lane = t & 31;
    const int wid = t >> 5;
    int carry = 0;
#pragma unroll
    for (int ch = 0; ch < 20; ch++) {
        int idx = ch * 1024 + t;
        int v = (idx < NN) ? g_counts[idx] : 0;
        int s = v;
#pragma unroll
        for (int off = 1; off < 32; off <<= 1) {
            int u = __shfl_up_sync(0xffffffffu, s, off);
            if (lane >= off) s += u;
        }
        if (lane == 31) wsums[wid] = s;
        __syncthreads();
        if (wid == 0) {
            int ws = wsums[lane];
#pragma unroll
            for (int off = 1; off < 32; off <<= 1) {
                int u = __shfl_up_sync(0xffffffffu, ws, off);
                if (lane >= off) ws += u;
            }
            wsums[lane] = ws;
        }
        __syncthreads();
        int blockoff = (wid > 0) ? wsums[wid - 1] : 0;
        int excl = s + blockoff + carry - v;
        if (idx < NN) {
            g_off[idx] = excl;
            g_cur[idx] = excl;
        }
        int total = wsums[31];
        __syncthreads();
        carry += total;
    }
    if (t == 0) g_off[NN] = carry;
}

__global__ void scatter_kernel() {
    int e = blockIdx.x * 1024 + threadIdx.x;
    int r = g_row[e];
    int p = atomicAdd(&g_cur[r], 1);
    g_scol[p] = g_col[e];
}

// ---------------- QKV projection via HMMA (mma.sync m16n8k16 fp16 -> fp32) ----------
// Block: 128 rows x 128 cols, 8 warps; warp w owns rows w*16..+15, all 128 cols.
// A = x tile fp16 smem [128][136] (pad -> conflict-free ldmatrix phases),
// B = W fp16 smem [128][136] (k-major; ldmatrix.trans gives the col-major frag).
// grid.y: 0 -> g_q fp32, 1 -> k halves, 2 -> v halves + fused psi MLP.
#define AH_HSTRIDE 136
__global__ void __launch_bounds__(256) gemm_qkv_mma(
    const float* __restrict__ Wq, const float* __restrict__ bq,
    const float* __restrict__ Wk, const float* __restrict__ bk,
    const float* __restrict__ Wv, const float* __restrict__ bv,
    const float* __restrict__ Wpsi, const float* __restrict__ bpsi) {
    extern __shared__ char smraw[];
    __half* Ah = (__half*)smraw;                          // 128*136*2 = 34816 B
    __half* Bh = (__half*)(smraw + 34816);                // 34816 B
    float*  vsm = (float*)smraw;                          // aliases Ah/Bh: 128*132*4 = 67584 B
    float*  Wp  = (float*)(smraw + 69632);                // 256 floats
    float*  bps = (float*)(smraw + 69632 + 1024);         // 16 floats
    float*  bs  = (float*)(smraw + 69632 + 1024 + 64);    // 128 floats

    const int t = threadIdx.x;
    const int r0 = blockIdx.x * 128;
    const int which = blockIdx.y;
    const float* W = (which == 0) ? Wq : (which == 1) ? Wk : Wv;
    const float* B = (which == 0) ? bq : (which == 1) ? bk : bv;

    Wp[t] = Wpsi[t];
    if (t < 16) bps[t] = bpsi[t];
    if (t < 128) bs[t] = B[t];

    // load A tile (fp16 x), zero-fill past NN
#pragma unroll
    for (int i = t; i < 128 * 16; i += 256) {
        int row = i >> 4, c8 = i & 15;
        int gr = r0 + row;
        uint4 val = make_uint4(0u, 0u, 0u, 0u);
        if (gr < NN) val = ((const uint4*)(g_xh + (size_t)gr * 128))[c8];
        *((uint4*)(Ah + row * AH_HSTRIDE + c8 * 8)) = val;
    }
    // load W -> fp16 smem
#pragma unroll
    for (int i = t; i < 128 * 32; i += 256) {
        int row = i >> 5, c4 = i & 31;
        float4 w = ((const float4*)W)[i];
        __half2 h0 = __floats2half2_rn(w.x, w.y);
        __half2 h1 = __floats2half2_rn(w.z, w.w);
        *((__half2*)(Bh + row * AH_HSTRIDE + c4 * 4))     = h0;
        *((__half2*)(Bh + row * AH_HSTRIDE + c4 * 4 + 2)) = h1;
    }
    __syncthreads();

    const int lane = t & 31;
    const int warp = t >> 5;
    const int wr0 = warp * 16;
    const int qr = lane >> 2;        // quad row
    const int qc = lane & 3;         // quad col

    float acc[16][4];
#pragma unroll
    for (int nt = 0; nt < 16; nt++) {
        float b0v = bs[nt * 8 + qc * 2];
        float b1v = bs[nt * 8 + qc * 2 + 1];
        acc[nt][0] = b0v; acc[nt][1] = b1v; acc[nt][2] = b0v; acc[nt][3] = b1v;
    }

    // per-lane ldmatrix address components
    const int mat = lane >> 3;
    const int rl8 = lane & 7;
    const int a_row = wr0 + rl8 + ((mat & 1) << 3);
    const int a_k8  = (mat >> 1) << 3;
    const int b_k   = rl8 + ((mat & 1) << 3);
    const int b_n8  = (mat >> 1) << 3;
    const unsigned a_base = smem_u32(Ah);
    const unsigned b_base = smem_u32(Bh);

#pragma unroll
    for (int kc = 0; kc < 8; kc++) {
        unsigned a0, a1, a2, a3;
        ldsm_x4(a0, a1, a2, a3,
                a_base + (unsigned)((a_row * AH_HSTRIDE + kc * 16 + a_k8) * 2));
#pragma unroll
        for (int nt2 = 0; nt2 < 8; nt2++) {
            unsigned b0, b1, b2, b3;
            ldsm_x4_t(b0, b1, b2, b3,
                      b_base + (unsigned)(((kc * 16 + b_k) * AH_HSTRIDE + nt2 * 16 + b_n8) * 2));
            mma16816(acc[2 * nt2],     a0, a1, a2, a3, b0, b1);
            mma16816(acc[2 * nt2 + 1], a0, a1, a2, a3, b2, b3);
        }
    }

    const int rloc0 = wr0 + qr;
    const int rloc1 = rloc0 + 8;
    const int gr0 = r0 + rloc0;
    const int gr1 = r0 + rloc1;

    if (which == 0) {
#pragma unroll
        for (int nt = 0; nt < 16; nt++) {
            int c = nt * 8 + qc * 2;
            if (gr0 < NN) *((float2*)(g_q + (size_t)gr0 * 128 + c)) = make_float2(acc[nt][0], acc[nt][1]);
            if (gr1 < NN) *((float2*)(g_q + (size_t)gr1 * 128 + c)) = make_float2(acc[nt][2], acc[nt][3]);
        }
    } else if (which == 1) {
#pragma unroll
        for (int nt = 0; nt < 16; nt++) {
            int c = nt * 8 + qc * 2;
            if (gr0 < NN) *((__half2*)(g_kvp + (size_t)gr0 * 384 + c)) = __floats2half2_rn(acc[nt][0], acc[nt][1]);
            if (gr1 < NN) *((__half2*)(g_kvp + (size_t)gr1 * 384 + c)) = __floats2half2_rn(acc[nt][2], acc[nt][3]);
        }
    } else {
        // v: halves to record, fp32 to vsm (aliases Ah/Bh) for the psi transpose
        __syncthreads();   // all warps done reading Ah/Bh
#pragma unroll
        for (int nt = 0; nt < 16; nt++) {
            int c = nt * 8 + qc * 2;
            if (gr0 < NN) *((__half2*)(g_kvp + (size_t)gr0 * 384 + 128 + c)) = __floats2half2_rn(acc[nt][0], acc[nt][1]);
            if (gr1 < NN) *((__half2*)(g_kvp + (size_t)gr1 * 384 + 128 + c)) = __floats2half2_rn(acc[nt][2], acc[nt][3]);
            *((float2*)(vsm + rloc0 * 132 + c)) = make_float2(acc[nt][0], acc[nt][1]);
            *((float2*)(vsm + rloc1 * 132 + c)) = make_float2(acc[nt][2], acc[nt][3]);
        }
        __syncthreads();
        // psi: thread t -> row t>>1, cols (t&1)*64..+63
        const int row = t >> 1;
        const int half = t & 1;
        const int gr = r0 + row;
        if (gr < NN) {
            __half* dst = g_kvp + (size_t)gr * 384 + 256;
            const float* vrow = vsm + row * 132;
#pragma unroll
            for (int j = 0; j < 64; j += 2) {
                const int c = half * 64 + j;
                const int head = c >> 4;
                const int d0 = c & 15, d1 = (c + 1) & 15;
                float s0 = bps[d0], s1 = bps[d1];
                const float* vh = vrow + head * 16;
#pragma unroll
                for (int d = 0; d < 16; d++) {
                    s0 = fmaf(vh[d], Wp[d * 16 + d0], s0);
                    s1 = fmaf(vh[d], Wp[d * 16 + d1], s1);
                }
                *((__half2*)(dst + c)) = __floats2half2_rn(tanhf(s0), tanhf(s1));
            }
        }
    }
}

// ---------------- fused edge pass: one warp per destination row ----------------
__global__ void __launch_bounds__(256) edge_kernel() {
    const int r = (blockIdx.x << 3) + (threadIdx.x >> 5);
    const int lane = threadIdx.x & 31;
    const int s0 = g_off[r];
    const int s1 = g_off[r + 1];
    const float4 qv = *((const float4*)(g_q + (size_t)r * 128) + lane);
    float4 alp = make_float4(0.f, 0.f, 0.f, 0.f);
    float4 abp = make_float4(0.f, 0.f, 0.f, 0.f);
    float ssum = 0.f;
    const uint2* kvp = (const uint2*)g_kvp;

    int e = s0;
    for (; e + 2 <= s1; e += 2) {
        const int c0 = g_scol[e];
        const int c1 = g_scol[e + 1];
        const uint2* b0 = kvp + c0 * 96 + lane;
        const uint2* b1 = kvp + c1 * 96 + lane;
        const uint2 k0 = b0[0],  k1 = b1[0];
        const uint2 v0 = b0[32], v1 = b1[32];
        const uint2 p0 = b0[64], p1 = b1[64];

        float2 k0a = __half22float2(*(const __half2*)&k0.x);
        float2 k0b = __half22float2(*(const __half2*)&k0.y);
        float2 k1a = __half22float2(*(const __half2*)&k1.x);
        float2 k1b = __half22float2(*(const __half2*)&k1.y);
        float d0 = fmaf(qv.x, k0a.x, fmaf(qv.y, k0a.y, fmaf(qv.z, k0b.x, qv.w * k0b.y)));
        float d1 = fmaf(qv.x, k1a.x, fmaf(qv.y, k1a.y, fmaf(qv.z, k1b.x, qv.w * k1b.y)));
        d0 += __shfl_xor_sync(0xffffffffu, d0, 1);
        d1 += __shfl_xor_sync(0xffffffffu, d1, 1);
        d0 += __shfl_xor_sync(0xffffffffu, d0, 2);
        d1 += __shfl_xor_sync(0xffffffffu, d1, 2);
        const float w0 = __expf(d0 * 0.25f);
        const float w1 = __expf(d1 * 0.25f);
        ssum += w0 + w1;

        float2 va = __half22float2(*(const __half2*)&v0.x);
        float2 vb = __half22float2(*(const __half2*)&v0.y);
        alp.x = fmaf(w0, va.x, alp.x); alp.y = fmaf(w0, va.y, alp.y);
        alp.z = fmaf(w0, vb.x, alp.z); alp.w = fmaf(w0, vb.y, alp.w);
        va = __half22float2(*(const __half2*)&v1.x);
        vb = __half22float2(*(const __half2*)&v1.y);
        alp.x = fmaf(w1, va.x, alp.x); alp.y = fmaf(w1, va.y, alp.y);
        alp.z = fmaf(w1, vb.x, alp.z); alp.w = fmaf(w1, vb.y, alp.w);

        float2 pa = __half22float2(*(const __half2*)&p0.x);
        float2 pb = __half22float2(*(const __half2*)&p0.y);
        abp.x = fmaf(w0, pa.x, abp.x); abp.y = fmaf(w0, pa.y, abp.y);
        abp.z = fmaf(w0, pb.x, abp.z); abp.w = fmaf(w0, pb.y, abp.w);
        pa = __half22float2(*(const __half2*)&p1.x);
        pb = __half22float2(*(const __half2*)&p1.y);
        abp.x = fmaf(w1, pa.x, abp.x); abp.y = fmaf(w1, pa.y, abp.y);
        abp.z = fmaf(w1, pb.x, abp.z); abp.w = fmaf(w1, pb.y, abp.w);
    }
    if (e < s1) {
        const int c0 = g_scol[e];
        const uint2* b0 = kvp + c0 * 96 + lane;
        const uint2 k0 = b0[0];
        const uint2 v0 = b0[32];
        const uint2 p0 = b0[64];
        float2 k0a = __half22float2(*(const __half2*)&k0.x);
        float2 k0b = __half22float2(*(const __half2*)&k0.y);
        float d0 = fmaf(qv.x, k0a.x, fmaf(qv.y, k0a.y, fmaf(qv.z, k0b.x, qv.w * k0b.y)));
        d0 += __shfl_xor_sync(0xffffffffu, d0, 1);
        d0 += __shfl_xor_sync(0xffffffffu, d0, 2);
        const float w0 = __expf(d0 * 0.25f);
        ssum += w0;
        float2 va = __half22float2(*(const __half2*)&v0.x);
        float2 vb = __half22float2(*(const __half2*)&v0.y);
        alp.x = fmaf(w0, va.x, alp.x); alp.y = fmaf(w0, va.y, alp.y);
        alp.z = fmaf(w0, vb.x, alp.z); alp.w = fmaf(w0, vb.y, alp.w);
        float2 pa = __half22float2(*(const __half2*)&p0.x);
        float2 pb = __half22float2(*(const __half2*)&p0.y);
        abp.x = fmaf(w0, pa.x, abp.x); abp.y = fmaf(w0, pa.y, abp.y);
        abp.z = fmaf(w0, pb.x, abp.z); abp.w = fmaf(w0, pb.y, abp.w);
    }
    const float inv = 1.f / (ssum + 1e-16f);
    float4 o;
    o.x = alp.x * inv; o.y = alp.y * inv; o.z = alp.z * inv; o.w = alp.w * inv;
    *((float4*)(g_hcat + (size_t)r * 256) + lane) = o;
    o.x = abp.x * inv; o.y = abp.y * inv; o.z = abp.z * inv; o.w = abp.w * inv;
    *((float4*)(g_hcat + (size_t)r * 256 + 128) + lane) = o;
}

// ---------------- output GEMM + residual + ReLU + LayerNorm (fp32, proven) ------
__global__ void __launch_bounds__(256) final_kernel(const float* __restrict__ X,
                                                    const float* __restrict__ Wo,
                                                    const float* __restrict__ bo,
                                                    const float* __restrict__ gamma,
                                                    const float* __restrict__ beta,
                                                    float* __restrict__ Y) {
    extern __shared__ float sm[];
    float* Ws = sm;               // [256 k][128 col]
    float* Hs = sm + 256 * 128;   // [256 k][68] transposed H tile (rows 0..63)

    const int t = threadIdx.x;
    const int r0 = blockIdx.x * 64;

    for (int i = t; i < 256 * 32; i += 256)
        ((float4*)Ws)[i] = ((const float4*)Wo)[i];
    for (int i = t; i < 64 * 64; i += 256) {
        int row = i >> 6, c4 = i & 63;
        int gr = r0 + row;
        float4 val = make_float4(0.f, 0.f, 0.f, 0.f);
        if (gr < NN) val = ((const float4*)(g_hcat + (size_t)gr * 256))[c4];
        Hs[(4 * c4 + 0) * 68 + row] = val.x;
        Hs[(4 * c4 + 1) * 68 + row] = val.y;
        Hs[(4 * c4 + 2) * 68 + row] = val.z;
        Hs[(4 * c4 + 3) * 68 + row] = val.w;
    }
    __syncthreads();

    const int tx = t & 15;
    const int ty = t >> 4;

    float acc[4][8];
    {
        float4 c0 = *((const float4*)(bo + tx * 4));
        float4 c1 = *((const float4*)(bo + 64 + tx * 4));
#pragma unroll
        for (int i = 0; i < 4; i++) {
            acc[i][0] = c0.x; acc[i][1] = c0.y; acc[i][2] = c0.z; acc[i][3] = c0.w;
            acc[i][4] = c1.x; acc[i][5] = c1.y; acc[i][6] = c1.z; acc[i][7] = c1.w;
        }
    }
#pragma unroll 4
    for (int k = 0; k < 256; k++) {
        float4 a  = *((const float4*)(Hs + k * 68 + ty * 4));
        float4 b0 = *((const float4*)(Ws + k * 128 + tx * 4));
        float4 b1 = *((const float4*)(Ws + k * 128 + 64 + tx * 4));
        float av[4] = {a.x, a.y, a.z, a.w};
        float bw[8] = {b0.x, b0.y, b0.z, b0.w, b1.x, b1.y, b1.z, b1.w};
#pragma unroll
        for (int i = 0; i < 4; i++)
#pragma unroll
            for (int j = 0; j < 8; j++)
                acc[i][j] = fmaf(av[i], bw[j], acc[i][j]);
    }

    const float4 gm0 = *((const float4*)(gamma + tx * 4));
    const float4 gm1 = *((const float4*)(gamma + 64 + tx * 4));
    const float4 bt0 = *((const float4*)(beta + tx * 4));
    const float4 bt1 = *((const float4*)(beta + 64 + tx * 4));

#pragma unroll
    for (int i = 0; i < 4; i++) {
        int gr = r0 + ty * 4 + i;
        bool ok = gr < NN;
        float4 x0 = make_float4(0.f, 0.f, 0.f, 0.f);
        float4 x1 = make_float4(0.f, 0.f, 0.f, 0.f);
        if (ok) {
            x0 = *((const float4*)(X + (size_t)gr * 128 + tx * 4));
            x1 = *((const float4*)(X + (size_t)gr * 128 + 64 + tx * 4));
        }
        float y[8];
        y[0] = x0.x + fmaxf(acc[i][0], 0.f);
        y[1] = x0.y + fmaxf(acc[i][1], 0.f);
        y[2] = x0.z + fmaxf(acc[i][2], 0.f);
        y[3] = x0.w + fmaxf(acc[i][3], 0.f);
        y[4] = x1.x + fmaxf(acc[i][4], 0.f);
        y[5] = x1.y + fmaxf(acc[i][5], 0.f);
        y[6] = x1.z + fmaxf(acc[i][6], 0.f);
        y[7] = x1.w + fmaxf(acc[i][7], 0.f);
        float ps = 0.f, pq = 0.f;
#pragma unroll
        for (int j = 0; j < 8; j++) { ps += y[j]; pq += y[j] * y[j]; }
#pragma unroll
        for (int off = 1; off < 16; off <<= 1) {
            ps += __shfl_xor_sync(0xffffffffu, ps, off);
            pq += __shfl_xor_sync(0xffffffffu, pq, off);
        }
        float mu = ps * (1.f / 128.f);
        float sq = pq * (1.f / 128.f);
        float rsig = rsqrtf(sq - mu * mu + 1e-5f);
        if (ok) {
            float4 o;
            o.x = (y[0] - mu) * rsig * gm0.x + bt0.x;
            o.y = (y[1] - mu) * rsig * gm0.y + bt0.y;
            o.z = (y[2] - mu) * rsig * gm0.z + bt0.z;
            o.w = (y[3] - mu) * rsig * gm0.w + bt0.w;
            *((float4*)(Y + (size_t)gr * 128 + tx * 4)) = o;
            o.x = (y[4] - mu) * rsig * gm1.x + bt1.x;
            o.y = (y[5] - mu) * rsig * gm1.y + bt1.y;
            o.z = (y[6] - mu) * rsig * gm1.z + bt1.z;
            o.w = (y[7] - mu) * rsig * gm1.w + bt1.w;
            *((float4*)(Y + (size_t)gr * 128 + 64 + tx * 4)) = o;
        }
    }
}

// ---------------- launch ----------------
extern "C" void kernel_launch(void* const* d_in, const int* in_sizes, int n_in,
                              void* d_out, int out_size) {
    const float* x     = (const float*)d_in[0];
    const void*  ei    = d_in[1];
    const float* Wq    = (const float*)d_in[2];
    const float* bq    = (const float*)d_in[3];
    const float* Wk    = (const float*)d_in[4];
    const float* bk    = (const float*)d_in[5];
    const float* Wv    = (const float*)d_in[6];
    const float* bv    = (const float*)d_in[7];
    const float* Wpsi  = (const float*)d_in[8];
    const float* bpsi  = (const float*)d_in[9];
    const float* Wo    = (const float*)d_in[10];
    const float* bo    = (const float*)d_in[11];
    const float* gamma = (const float*)d_in[12];
    const float* beta  = (const float*)d_in[13];
    float* out = (float*)d_out;
    (void)in_sizes; (void)n_in; (void)out_size;

    const int SMEM_MMA   = 69632 + 1024 + 64 + 512;       // 71232 B
    const int SMEM_FINAL = (256 * 128 + 256 * 68) * 4;    // 200704 B
    (void)cudaFuncSetAttribute(gemm_qkv_mma, cudaFuncAttributeMaxDynamicSharedMemorySize, SMEM_MMA);
    (void)cudaFuncSetAttribute(final_kernel, cudaFuncAttributeMaxDynamicSharedMemorySize, SMEM_FINAL);

    // edge preprocessing (counting sort by destination row)
    detect_zero_kernel<<<20, 1024>>>((const int*)ei);
    x2h_kernel<<<1250, 256>>>(x);
    decode_hist_kernel<<<EE / 1024, 1024>>>(ei);
    scan_kernel<<<1, 1024>>>();
    scatter_kernel<<<EE / 1024, 1024>>>();

    // node-level projections: tensor-core QKV (+ fused psi on the v path)
    gemm_qkv_mma<<<dim3(157, 3), 256, SMEM_MMA>>>(Wq, bq, Wk, bk, Wv, bv, Wpsi, bpsi);

    // fused attention edge pass
    edge_kernel<<<NN / 8, 256>>>();

    // output projection + residual + ReLU + LayerNorm
    final_kernel<<<313, 256, SMEM_FINAL>>>(x, Wo, bo, gamma, beta, out);
}

// round 12
// speedup vs baseline: 1.7133x; 1.7133x over previous
#include <cuda_runtime.h>
#include <cuda_fp16.h>
#include <math.h>

#define NN 20000
#define EE 640000

// ---------------- scratch (static device globals; no allocation) ----------------
__device__ float  g_q[NN * 128];
__device__ __half g_kvp[NN * 384];        // packed per-node record: k[128] | v[128] | psi[128]
__device__ float  g_hcat[NN * 256];
__device__ int    g_row[EE];
__device__ int    g_col[EE];
__device__ int    g_scol[EE];
__device__ int    g_counts[NN];
__device__ int    g_off[NN + 1];
__device__ int    g_cur[NN];
__device__ int    g_is64;

// ---------------- fused: zero counts + edge_index dtype detection ----------------
__global__ void detect_zero_kernel(const int* __restrict__ p) {
    int i = blockIdx.x * 1024 + threadIdx.x;
    if (i < NN) g_counts[i] = 0;
    if (blockIdx.x == 0 && threadIdx.x < 32) {
        int l = threadIdx.x;
        int bad = (p[2 * l + 1] != 0);
        unsigned m = __ballot_sync(0xffffffffu, bad);
        if (l == 0) g_is64 = (m == 0u) ? 1 : 0;
    }
}

// ---------------- fused decode + histogram ----------------
__global__ void decode_hist_kernel(const void* __restrict__ ei) {
    int e = blockIdx.x * 1024 + threadIdx.x;
    int r, c;
    if (g_is64) {
        const long long* q = (const long long*)ei;
        r = (int)q[e]; c = (int)q[EE + e];
    } else {
        const int* q = (const int*)ei;
        r = q[e]; c = q[EE + e];
    }
    g_row[e] = r;
    g_col[e] = c;
    atomicAdd(&g_counts[r], 1);
}

// ---------------- exclusive scan: all 20 chunks in parallel, 3 barriers total ----
// Phase 1: every thread loads its element of each chunk (MLP=20) and does an
// independent per-chunk warp scan. Phase 2: 20 warps (one per chunk) scan the
// 32 warp sums. Phase 3: one warp scans the 20 chunk totals. Then recombine.
__global__ void scan_kernel() {
    __shared__ int wsums[20][33];
    __shared__ int ctot[32];
    __shared__ int coff[21];
    const int t = threadIdx.x;
    const int lane = t & 31;
    const int wid = t >> 5;

    int val[20], inc[20];
#pragma unroll
    for (int ch = 0; ch < 20; ch++) {
        int idx = ch * 1024 + t;
        val[ch] = (idx < NN) ? g_counts[idx] : 0;
    }
#pragma unroll
    for (int ch = 0; ch < 20; ch++) {
        int s = val[ch];
#pragma unroll
        for (int off = 1; off < 32; off <<= 1) {
            int u = __shfl_up_sync(0xffffffffu, s, off);
            if (lane >= off) s += u;
        }
        inc[ch] = s;
        if (lane == 31) wsums[ch][wid] = s;
    }
    __syncthreads();
    if (wid < 20) {
        int ws = wsums[wid][lane];
#pragma unroll
        for (int off = 1; off < 32; off <<= 1) {
            int u = __shfl_up_sync(0xffffffffu, ws, off);
            if (lane >= off) ws += u;
        }
        wsums[wid][lane] = ws;                 // inclusive over warps within chunk
        if (lane == 31) ctot[wid] = ws;        // chunk total
    }
    __syncthreads();
    if (wid == 0) {
        int c = (lane < 20) ? ctot[lane] : 0;
#pragma unroll
        for (int off = 1; off < 32; off <<= 1) {
            int u = __shfl_up_sync(0xffffffffu, c, off);
            if (lane >= off) c += u;
        }
        if (lane < 20) coff[lane + 1] = c;     // inclusive -> offset of next chunk
        if (lane == 0) coff[0] = 0;
    }
    __syncthreads();
#pragma unroll
    for (int ch = 0; ch < 20; ch++) {
        int idx = ch * 1024 + t;
        if (idx < NN) {
            int blockoff = (wid > 0) ? wsums[ch][wid - 1] : 0;
            int excl = inc[ch] - val[ch] + blockoff + coff[ch];
            g_off[idx] = excl;
            g_cur[idx] = excl;
        }
    }
    if (t == 0) g_off[NN] = coff[20];
}

__global__ void scatter_kernel() {
    int e = blockIdx.x * 1024 + threadIdx.x;
    int r = g_row[e];
    int p = atomicAdd(&g_cur[r], 1);
    g_scol[p] = g_col[e];
}

// ---------------- fused QKV GEMM (+ psi MLP on the v path) ----------------
// Block: 64 rows x 128 cols, 256 threads, each thread 4 rows x 8 cols.
// X tile stored k-major (transposed) so a-frag is one LDS.128 (broadcast).
// grid.y: 0 -> g_q fp32, 1 -> k halves into kvp[+0],
//         2 -> v halves into kvp[+128] AND psi=tanh(v@Wpsi+bpsi) into kvp[+256].
__global__ void __launch_bounds__(256) gemm_qkv(const float* __restrict__ X,
                                                const float* __restrict__ Wq, const float* __restrict__ bq,
                                                const float* __restrict__ Wk, const float* __restrict__ bk,
                                                const float* __restrict__ Wv, const float* __restrict__ bv,
                                                const float* __restrict__ Wpsi, const float* __restrict__ bpsi) {
    extern __shared__ float sm[];
    float* Xs = sm;              // [128 k][68] transposed X tile (rows 0..63)
    float* Ws = sm + 128 * 68;   // [128 k][128 col]
    float* Wp  = sm + 128 * 68 + 128 * 128;   // 256 floats (Wpsi)
    float* bps = Wp + 256;                    // 16 floats (bpsi)

    const int t = threadIdx.x;
    const int r0 = blockIdx.x * 64;
    const int which = blockIdx.y;
    const float* W = (which == 0) ? Wq : (which == 1) ? Wk : Wv;
    const float* B = (which == 0) ? bq : (which == 1) ? bk : bv;

    Wp[t] = Wpsi[t];                 // 256 threads = 256 elems
    if (t < 16) bps[t] = bpsi[t];

    for (int i = t; i < 64 * 32; i += 256) {
        int row = i >> 5, c4 = i & 31;
        int gr = r0 + row;
        float4 val = make_float4(0.f, 0.f, 0.f, 0.f);
        if (gr < NN) val = ((const float4*)(X + (size_t)gr * 128))[c4];
        Xs[(4 * c4 + 0) * 68 + row] = val.x;
        Xs[(4 * c4 + 1) * 68 + row] = val.y;
        Xs[(4 * c4 + 2) * 68 + row] = val.z;
        Xs[(4 * c4 + 3) * 68 + row] = val.w;
    }
    for (int i = t; i < 128 * 32; i += 256)
        ((float4*)Ws)[i] = ((const float4*)W)[i];
    __syncthreads();

    const int tx = t & 15;       // col group: cols tx*4..+3 and 64+tx*4..+3
    const int ty = t >> 4;       // row group: rows ty*4..+3

    float acc[4][8];
    {
        float4 c0 = *((const float4*)(B + tx * 4));
        float4 c1 = *((const float4*)(B + 64 + tx * 4));
#pragma unroll
        for (int i = 0; i < 4; i++) {
            acc[i][0] = c0.x; acc[i][1] = c0.y; acc[i][2] = c0.z; acc[i][3] = c0.w;
            acc[i][4] = c1.x; acc[i][5] = c1.y; acc[i][6] = c1.z; acc[i][7] = c1.w;
        }
    }

#pragma unroll 4
    for (int k = 0; k < 128; k++) {
        float4 a  = *((const float4*)(Xs + k * 68 + ty * 4));
        float4 b0 = *((const float4*)(Ws + k * 128 + tx * 4));
        float4 b1 = *((const float4*)(Ws + k * 128 + 64 + tx * 4));
        float av[4] = {a.x, a.y, a.z, a.w};
        float bw[8] = {b0.x, b0.y, b0.z, b0.w, b1.x, b1.y, b1.z, b1.w};
#pragma unroll
        for (int i = 0; i < 4; i++)
#pragma unroll
            for (int j = 0; j < 8; j++)
                acc[i][j] = fmaf(av[i], bw[j], acc[i][j]);
    }

#pragma unroll
    for (int i = 0; i < 4; i++) {
        int gr = r0 + ty * 4 + i;
        if (gr >= NN) continue;
        if (which == 0) {
            *((float4*)(g_q + (size_t)gr * 128 + tx * 4)) =
                make_float4(acc[i][0], acc[i][1], acc[i][2], acc[i][3]);
            *((float4*)(g_q + (size_t)gr * 128 + 64 + tx * 4)) =
                make_float4(acc[i][4], acc[i][5], acc[i][6], acc[i][7]);
        } else {
            // halves into packed record: k at +0, v at +128
            __half* dst = g_kvp + (size_t)gr * 384 + ((which == 1) ? 0 : 128);
            *((__half2*)(dst + tx * 4))     = __floats2half2_rn(acc[i][0], acc[i][1]);
            *((__half2*)(dst + tx * 4 + 2)) = __floats2half2_rn(acc[i][2], acc[i][3]);
            *((__half2*)(dst + 64 + tx * 4))     = __floats2half2_rn(acc[i][4], acc[i][5]);
            *((__half2*)(dst + 64 + tx * 4 + 2)) = __floats2half2_rn(acc[i][6], acc[i][7]);
        }
    }

    if (which == 2) {
        // stage fp32 v tile into smem (reuse Xs region) for the head transpose
        float* vsm = sm;          // 64 x 132
        __syncthreads();          // everyone done with Xs/Ws
#pragma unroll
        for (int i = 0; i < 4; i++) {
            int row = ty * 4 + i;
            vsm[row * 132 + tx * 4 + 0] = acc[i][0];
            vsm[row * 132 + tx * 4 + 1] = acc[i][1];
            vsm[row * 132 + tx * 4 + 2] = acc[i][2];
            vsm[row * 132 + tx * 4 + 3] = acc[i][3];
            vsm[row * 132 + 64 + tx * 4 + 0] = acc[i][4];
            vsm[row * 132 + 64 + tx * 4 + 1] = acc[i][5];
            vsm[row * 132 + 64 + tx * 4 + 2] = acc[i][6];
            vsm[row * 132 + 64 + tx * 4 + 3] = acc[i][7];
        }
        __syncthreads();
        // psi: thread t handles row = t>>2, cols (t&3)*32 .. +31 (pairs)
        const int row = t >> 2;
        const int grp = t & 3;
        const int gr = r0 + row;
        if (gr < NN) {
            __half* dst = g_kvp + (size_t)gr * 384 + 256;
            const float* vrow = vsm + row * 132;
#pragma unroll
            for (int j = 0; j < 32; j += 2) {
                const int c = grp * 32 + j;          // even -> c, c+1 share a head
                const int head = c >> 4;
                const int d0 = c & 15, d1 = (c + 1) & 15;
                float s0 = bps[d0], s1 = bps[d1];
                const float* vh = vrow + head * 16;
#pragma unroll
                for (int d = 0; d < 16; d++) {
                    s0 = fmaf(vh[d], Wp[d * 16 + d0], s0);
                    s1 = fmaf(vh[d], Wp[d * 16 + d1], s1);
                }
                *((__half2*)(dst + c)) = __floats2half2_rn(tanhf(s0), tanhf(s1));
            }
        }
    }
}

// ---------------- fused edge pass: one warp per destination row ----------------
__global__ void __launch_bounds__(256) edge_kernel() {
    const int r = (blockIdx.x << 3) + (threadIdx.x >> 5);
    const int lane = threadIdx.x & 31;
    const int s0 = g_off[r];
    const int s1 = g_off[r + 1];
    const float4 qv = *((const float4*)(g_q + (size_t)r * 128) + lane);
    float4 alp = make_float4(0.f, 0.f, 0.f, 0.f);
    float4 abp = make_float4(0.f, 0.f, 0.f, 0.f);
    float ssum = 0.f;
    const uint2* kvp = (const uint2*)g_kvp;   // 96 uint2 (=384 halves) per node

    int e = s0;
    for (; e + 2 <= s1; e += 2) {
        const int c0 = g_scol[e];
        const int c1 = g_scol[e + 1];
        const uint2* b0 = kvp + c0 * 96 + lane;
        const uint2* b1 = kvp + c1 * 96 + lane;
        const uint2 k0 = b0[0],  k1 = b1[0];
        const uint2 v0 = b0[32], v1 = b1[32];
        const uint2 p0 = b0[64], p1 = b1[64];

        float2 k0a = __half22float2(*(const __half2*)&k0.x);
        float2 k0b = __half22float2(*(const __half2*)&k0.y);
        float2 k1a = __half22float2(*(const __half2*)&k1.x);
        float2 k1b = __half22float2(*(const __half2*)&k1.y);
        float d0 = fmaf(qv.x, k0a.x, fmaf(qv.y, k0a.y, fmaf(qv.z, k0b.x, qv.w * k0b.y)));
        float d1 = fmaf(qv.x, k1a.x, fmaf(qv.y, k1a.y, fmaf(qv.z, k1b.x, qv.w * k1b.y)));
        d0 += __shfl_xor_sync(0xffffffffu, d0, 1);
        d1 += __shfl_xor_sync(0xffffffffu, d1, 1);
        d0 += __shfl_xor_sync(0xffffffffu, d0, 2);
        d1 += __shfl_xor_sync(0xffffffffu, d1, 2);
        const float w0 = __expf(d0 * 0.25f);
        const float w1 = __expf(d1 * 0.25f);
        ssum += w0 + w1;

        float2 va = __half22float2(*(const __half2*)&v0.x);
        float2 vb = __half22float2(*(const __half2*)&v0.y);
        alp.x = fmaf(w0, va.x, alp.x); alp.y = fmaf(w0, va.y, alp.y);
        alp.z = fmaf(w0, vb.x, alp.z); alp.w = fmaf(w0, vb.y, alp.w);
        va = __half22float2(*(const __half2*)&v1.x);
        vb = __half22float2(*(const __half2*)&v1.y);
        alp.x = fmaf(w1, va.x, alp.x); alp.y = fmaf(w1, va.y, alp.y);
        alp.z = fmaf(w1, vb.x, alp.z); alp.w = fmaf(w1, vb.y, alp.w);

        float2 pa = __half22float2(*(const __half2*)&p0.x);
        float2 pb = __half22float2(*(const __half2*)&p0.y);
        abp.x = fmaf(w0, pa.x, abp.x); abp.y = fmaf(w0, pa.y, abp.y);
        abp.z = fmaf(w0, pb.x, abp.z); abp.w = fmaf(w0, pb.y, abp.w);
        pa = __half22float2(*(const __half2*)&p1.x);
        pb = __half22float2(*(const __half2*)&p1.y);
        abp.x = fmaf(w1, pa.x, abp.x); abp.y = fmaf(w1, pa.y, abp.y);
        abp.z = fmaf(w1, pb.x, abp.z); abp.w = fmaf(w1, pb.y, abp.w);
    }
    if (e < s1) {
        const int c0 = g_scol[e];
        const uint2* b0 = kvp + c0 * 96 + lane;
        const uint2 k0 = b0[0];
        const uint2 v0 = b0[32];
        const uint2 p0 = b0[64];
        float2 k0a = __half22float2(*(const __half2*)&k0.x);
        float2 k0b = __half22float2(*(const __half2*)&k0.y);
        float d0 = fmaf(qv.x, k0a.x, fmaf(qv.y, k0a.y, fmaf(qv.z, k0b.x, qv.w * k0b.y)));
        d0 += __shfl_xor_sync(0xffffffffu, d0, 1);
        d0 += __shfl_xor_sync(0xffffffffu, d0, 2);
        const float w0 = __expf(d0 * 0.25f);
        ssum += w0;
        float2 va = __half22float2(*(const __half2*)&v0.x);
        float2 vb = __half22float2(*(const __half2*)&v0.y);
        alp.x = fmaf(w0, va.x, alp.x); alp.y = fmaf(w0, va.y, alp.y);
        alp.z = fmaf(w0, vb.x, alp.z); alp.w = fmaf(w0, vb.y, alp.w);
        float2 pa = __half22float2(*(const __half2*)&p0.x);
        float2 pb = __half22float2(*(const __half2*)&p0.y);
        abp.x = fmaf(w0, pa.x, abp.x); abp.y = fmaf(w0, pa.y, abp.y);
        abp.z = fmaf(w0, pb.x, abp.z); abp.w = fmaf(w0, pb.y, abp.w);
    }
    const float inv = 1.f / (ssum + 1e-16f);
    float4 o;
    o.x = alp.x * inv; o.y = alp.y * inv; o.z = alp.z * inv; o.w = alp.w * inv;
    *((float4*)(g_hcat + (size_t)r * 256) + lane) = o;
    o.x = abp.x * inv; o.y = abp.y * inv; o.z = abp.z * inv; o.w = abp.w * inv;
    *((float4*)(g_hcat + (size_t)r * 256 + 128) + lane) = o;
}

// ---------------- output GEMM + residual + ReLU + LayerNorm ----------------
__global__ void __launch_bounds__(256) final_kernel(const float* __restrict__ X,
                                                    const float* __restrict__ Wo,
                                                    const float* __restrict__ bo,
                                                    const float* __restrict__ gamma,
                                                    const float* __restrict__ beta,
                                                    float* __restrict__ Y) {
    extern __shared__ float sm[];
    float* Ws = sm;               // [256 k][128 col]
    float* Hs = sm + 256 * 128;   // [256 k][68] transposed H tile (rows 0..63)

    const int t = threadIdx.x;
    const int r0 = blockIdx.x * 64;

    for (int i = t; i < 256 * 32; i += 256)
        ((float4*)Ws)[i] = ((const float4*)Wo)[i];
    for (int i = t; i < 64 * 64; i += 256) {
        int row = i >> 6, c4 = i & 63;
        int gr = r0 + row;
        float4 val = make_float4(0.f, 0.f, 0.f, 0.f);
        if (gr < NN) val = ((const float4*)(g_hcat + (size_t)gr * 256))[c4];
        Hs[(4 * c4 + 0) * 68 + row] = val.x;
        Hs[(4 * c4 + 1) * 68 + row] = val.y;
        Hs[(4 * c4 + 2) * 68 + row] = val.z;
        Hs[(4 * c4 + 3) * 68 + row] = val.w;
    }
    __syncthreads();

    const int tx = t & 15;
    const int ty = t >> 4;

    float acc[4][8];
    {
        float4 c0 = *((const float4*)(bo + tx * 4));
        float4 c1 = *((const float4*)(bo + 64 + tx * 4));
#pragma unroll
        for (int i = 0; i < 4; i++) {
            acc[i][0] = c0.x; acc[i][1] = c0.y; acc[i][2] = c0.z; acc[i][3] = c0.w;
            acc[i][4] = c1.x; acc[i][5] = c1.y; acc[i][6] = c1.z; acc[i][7] = c1.w;
        }
    }
#pragma unroll 4
    for (int k = 0; k < 256; k++) {
        float4 a  = *((const float4*)(Hs + k * 68 + ty * 4));
        float4 b0 = *((const float4*)(Ws + k * 128 + tx * 4));
        float4 b1 = *((const float4*)(Ws + k * 128 + 64 + tx * 4));
        float av[4] = {a.x, a.y, a.z, a.w};
        float bw[8] = {b0.x, b0.y, b0.z, b0.w, b1.x, b1.y, b1.z, b1.w};
#pragma unroll
        for (int i = 0; i < 4; i++)
#pragma unroll
            for (int j = 0; j < 8; j++)
                acc[i][j] = fmaf(av[i], bw[j], acc[i][j]);
    }

    const float4 gm0 = *((const float4*)(gamma + tx * 4));
    const float4 gm1 = *((const float4*)(gamma + 64 + tx * 4));
    const float4 bt0 = *((const float4*)(beta + tx * 4));
    const float4 bt1 = *((const float4*)(beta + 64 + tx * 4));

#pragma unroll
    for (int i = 0; i < 4; i++) {
        int gr = r0 + ty * 4 + i;
        bool ok = gr < NN;
        float4 x0 = make_float4(0.f, 0.f, 0.f, 0.f);
        float4 x1 = make_float4(0.f, 0.f, 0.f, 0.f);
        if (ok) {
            x0 = *((const float4*)(X + (size_t)gr * 128 + tx * 4));
            x1 = *((const float4*)(X + (size_t)gr * 128 + 64 + tx * 4));
        }
        float y[8];
        y[0] = x0.x + fmaxf(acc[i][0], 0.f);
        y[1] = x0.y + fmaxf(acc[i][1], 0.f);
        y[2] = x0.z + fmaxf(acc[i][2], 0.f);
        y[3] = x0.w + fmaxf(acc[i][3], 0.f);
        y[4] = x1.x + fmaxf(acc[i][4], 0.f);
        y[5] = x1.y + fmaxf(acc[i][5], 0.f);
        y[6] = x1.z + fmaxf(acc[i][6], 0.f);
        y[7] = x1.w + fmaxf(acc[i][7], 0.f);
        float ps = 0.f, pq = 0.f;
#pragma unroll
        for (int j = 0; j < 8; j++) { ps += y[j]; pq += y[j] * y[j]; }
#pragma unroll
        for (int off = 1; off < 16; off <<= 1) {
            ps += __shfl_xor_sync(0xffffffffu, ps, off);
            pq += __shfl_xor_sync(0xffffffffu, pq, off);
        }
        float mu = ps * (1.f / 128.f);
        float sq = pq * (1.f / 128.f);
        float rsig = rsqrtf(sq - mu * mu + 1e-5f);
        if (ok) {
            float4 o;
            o.x = (y[0] - mu) * rsig * gm0.x + bt0.x;
            o.y = (y[1] - mu) * rsig * gm0.y + bt0.y;
            o.z = (y[2] - mu) * rsig * gm0.z + bt0.z;
            o.w = (y[3] - mu) * rsig * gm0.w + bt0.w;
            *((float4*)(Y + (size_t)gr * 128 + tx * 4)) = o;
            o.x = (y[4] - mu) * rsig * gm1.x + bt1.x;
            o.y = (y[5] - mu) * rsig * gm1.y + bt1.y;
            o.z = (y[6] - mu) * rsig * gm1.z + bt1.z;
            o.w = (y[7] - mu) * rsig * gm1.w + bt1.w;
            *((float4*)(Y + (size_t)gr * 128 + 64 + tx * 4)) = o;
        }
    }
}

// ---------------- launch ----------------
extern "C" void kernel_launch(void* const* d_in, const int* in_sizes, int n_in,
                              void* d_out, int out_size) {
    const float* x     = (const float*)d_in[0];
    const void*  ei    = d_in[1];
    const float* Wq    = (const float*)d_in[2];
    const float* bq    = (const float*)d_in[3];
    const float* Wk    = (const float*)d_in[4];
    const float* bk    = (const float*)d_in[5];
    const float* Wv    = (const float*)d_in[6];
    const float* bv    = (const float*)d_in[7];
    const float* Wpsi  = (const float*)d_in[8];
    const float* bpsi  = (const float*)d_in[9];
    const float* Wo    = (const float*)d_in[10];
    const float* bo    = (const float*)d_in[11];
    const float* gamma = (const float*)d_in[12];
    const float* beta  = (const float*)d_in[13];
    float* out = (float*)d_out;
    (void)in_sizes; (void)n_in; (void)out_size;

    const int SMEM_QKV   = (128 * 68 + 128 * 128 + 256 + 16) * 4;  // 101440 B
    const int SMEM_FINAL = (256 * 128 + 256 * 68) * 4;             // 200704 B
    (void)cudaFuncSetAttribute(gemm_qkv,     cudaFuncAttributeMaxDynamicSharedMemorySize, SMEM_QKV);
    (void)cudaFuncSetAttribute(final_kernel, cudaFuncAttributeMaxDynamicSharedMemorySize, SMEM_FINAL);

    // edge preprocessing (counting sort by destination row)
    detect_zero_kernel<<<20, 1024>>>((const int*)ei);
    decode_hist_kernel<<<EE / 1024, 1024>>>(ei);
    scan_kernel<<<1, 1024>>>();
    scatter_kernel<<<EE / 1024, 1024>>>();

    // node-level projections (fused QKV + psi via grid.y)
    gemm_qkv<<<dim3(313, 3), 256, SMEM_QKV>>>(x, Wq, bq, Wk, bk, Wv, bv, Wpsi, bpsi);

    // fused attention edge pass
    edge_kernel<<<NN / 8, 256>>>();

    // output projection + residual + ReLU + LayerNorm
    final_kernel<<<313, 256, SMEM_FINAL>>>(x, Wo, bo, gamma, beta, out);
}

// round 17
// speedup vs baseline: 1.7522x; 1.0227x over previous
#include <cuda_runtime.h>
#include <cuda_fp16.h>
#include <math.h>

#define NN 20000
#define EE 640000

// ---------------- scratch (static device globals; no allocation) ----------------
__device__ float  g_q[NN * 128];
__device__ __half g_kvp[NN * 384];        // packed per-node record: k[128] | v[128] | psi[128]
__device__ float  g_hcat[NN * 256];
__device__ int    g_row[EE];
__device__ int    g_col[EE];
__device__ int    g_scol[EE];
__device__ int    g_counts[NN];
__device__ int    g_off[NN + 1];
__device__ int    g_cur[NN];
__device__ int    g_is64;

// ---------------- fused: zero counts + edge_index dtype detection ----------------
__global__ void detect_zero_kernel(const int* __restrict__ p) {
    int i = blockIdx.x * 1024 + threadIdx.x;
    if (i < NN) g_counts[i] = 0;
    if (blockIdx.x == 0 && threadIdx.x < 32) {
        int l = threadIdx.x;
        int bad = (p[2 * l + 1] != 0);
        unsigned m = __ballot_sync(0xffffffffu, bad);
        if (l == 0) g_is64 = (m == 0u) ? 1 : 0;
    }
}

// ---------------- fused decode + histogram ----------------
__global__ void decode_hist_kernel(const void* __restrict__ ei) {
    int e = blockIdx.x * 1024 + threadIdx.x;
    int r, c;
    if (g_is64) {
        const long long* q = (const long long*)ei;
        r = (int)q[e]; c = (int)q[EE + e];
    } else {
        const int* q = (const int*)ei;
        r = q[e]; c = q[EE + e];
    }
    g_row[e] = r;
    g_col[e] = c;
    atomicAdd(&g_counts[r], 1);
}

// ---------------- exclusive scan: all 20 chunks in parallel, 3 barriers total ----
__global__ void scan_kernel() {
    __shared__ int wsums[20][33];
    __shared__ int ctot[32];
    __shared__ int coff[21];
    const int t = threadIdx.x;
    const int lane = t & 31;
    const int wid = t >> 5;

    int val[20], inc[20];
#pragma unroll
    for (int ch = 0; ch < 20; ch++) {
        int idx = ch * 1024 + t;
        val[ch] = (idx < NN) ? g_counts[idx] : 0;
    }
#pragma unroll
    for (int ch = 0; ch < 20; ch++) {
        int s = val[ch];
#pragma unroll
        for (int off = 1; off < 32; off <<= 1) {
            int u = __shfl_up_sync(0xffffffffu, s, off);
            if (lane >= off) s += u;
        }
        inc[ch] = s;
        if (lane == 31) wsums[ch][wid] = s;
    }
    __syncthreads();
    if (wid < 20) {
        int ws = wsums[wid][lane];
#pragma unroll
        for (int off = 1; off < 32; off <<= 1) {
            int u = __shfl_up_sync(0xffffffffu, ws, off);
            if (lane >= off) ws += u;
        }
        wsums[wid][lane] = ws;
        if (lane == 31) ctot[wid] = ws;
    }
    __syncthreads();
    if (wid == 0) {
        int c = (lane < 20) ? ctot[lane] : 0;
#pragma unroll
        for (int off = 1; off < 32; off <<= 1) {
            int u = __shfl_up_sync(0xffffffffu, c, off);
            if (lane >= off) c += u;
        }
        if (lane < 20) coff[lane + 1] = c;
        if (lane == 0) coff[0] = 0;
    }
    __syncthreads();
#pragma unroll
    for (int ch = 0; ch < 20; ch++) {
        int idx = ch * 1024 + t;
        if (idx < NN) {
            int blockoff = (wid > 0) ? wsums[ch][wid - 1] : 0;
            int excl = inc[ch] - val[ch] + blockoff + coff[ch];
            g_off[idx] = excl;
            g_cur[idx] = excl;
        }
    }
    if (t == 0) g_off[NN] = coff[20];
}

__global__ void scatter_kernel() {
    int e = blockIdx.x * 1024 + threadIdx.x;
    int r = g_row[e];
    int p = atomicAdd(&g_cur[r], 1);
    g_scol[p] = g_col[e];
}

// ---------------- fused QKV GEMM (+ psi MLP on the v path) ----------------
// Block: 64 rows x 128 cols, 256 threads, each thread 4 rows x 8 cols.
// X tile stored k-major (transposed) so a-frag is one LDS.128 (broadcast).
// grid.y: 0 -> g_q fp32, 1 -> k halves into kvp[+0],
//         2 -> v halves into kvp[+128] AND psi=tanh(v@Wpsi+bpsi) into kvp[+256].
__global__ void __launch_bounds__(256) gemm_qkv(const float* __restrict__ X,
                                                const float* __restrict__ Wq, const float* __restrict__ bq,
                                                const float* __restrict__ Wk, const float* __restrict__ bk,
                                                const float* __restrict__ Wv, const float* __restrict__ bv,
                                                const float* __restrict__ Wpsi, const float* __restrict__ bpsi) {
    extern __shared__ float sm[];
    float* Xs = sm;              // [128 k][68] transposed X tile (rows 0..63)
    float* Ws = sm + 128 * 68;   // [128 k][128 col]
    float* Wp  = sm + 128 * 68 + 128 * 128;   // 256 floats (Wpsi)
    float* bps = Wp + 256;                    // 16 floats (bpsi)

    const int t = threadIdx.x;
    const int r0 = blockIdx.x * 64;
    const int which = blockIdx.y;
    const float* W = (which == 0) ? Wq : (which == 1) ? Wk : Wv;
    const float* B = (which == 0) ? bq : (which == 1) ? bk : bv;

    Wp[t] = Wpsi[t];                 // 256 threads = 256 elems
    if (t < 16) bps[t] = bpsi[t];

    for (int i = t; i < 64 * 32; i += 256) {
        int row = i >> 5, c4 = i & 31;
        int gr = r0 + row;
        float4 val = make_float4(0.f, 0.f, 0.f, 0.f);
        if (gr < NN) val = ((const float4*)(X + (size_t)gr * 128))[c4];
        Xs[(4 * c4 + 0) * 68 + row] = val.x;
        Xs[(4 * c4 + 1) * 68 + row] = val.y;
        Xs[(4 * c4 + 2) * 68 + row] = val.z;
        Xs[(4 * c4 + 3) * 68 + row] = val.w;
    }
    for (int i = t; i < 128 * 32; i += 256)
        ((float4*)Ws)[i] = ((const float4*)W)[i];
    __syncthreads();

    const int tx = t & 15;       // col group: cols tx*4..+3 and 64+tx*4..+3
    const int ty = t >> 4;       // row group: rows ty*4..+3

    float acc[4][8];
    {
        float4 c0 = *((const float4*)(B + tx * 4));
        float4 c1 = *((const float4*)(B + 64 + tx * 4));
#pragma unroll
        for (int i = 0; i < 4; i++) {
            acc[i][0] = c0.x; acc[i][1] = c0.y; acc[i][2] = c0.z; acc[i][3] = c0.w;
            acc[i][4] = c1.x; acc[i][5] = c1.y; acc[i][6] = c1.z; acc[i][7] = c1.w;
        }
    }

#pragma unroll 4
    for (int k = 0; k < 128; k++) {
        float4 a  = *((const float4*)(Xs + k * 68 + ty * 4));
        float4 b0 = *((const float4*)(Ws + k * 128 + tx * 4));
        float4 b1 = *((const float4*)(Ws + k * 128 + 64 + tx * 4));
        float av[4] = {a.x, a.y, a.z, a.w};
        float bw[8] = {b0.x, b0.y, b0.z, b0.w, b1.x, b1.y, b1.z, b1.w};
#pragma unroll
        for (int i = 0; i < 4; i++)
#pragma unroll
            for (int j = 0; j < 8; j++)
                acc[i][j] = fmaf(av[i], bw[j], acc[i][j]);
    }

#pragma unroll
    for (int i = 0; i < 4; i++) {
        int gr = r0 + ty * 4 + i;
        if (gr >= NN) continue;
        if (which == 0) {
            *((float4*)(g_q + (size_t)gr * 128 + tx * 4)) =
                make_float4(acc[i][0], acc[i][1], acc[i][2], acc[i][3]);
            *((float4*)(g_q + (size_t)gr * 128 + 64 + tx * 4)) =
                make_float4(acc[i][4], acc[i][5], acc[i][6], acc[i][7]);
        } else {
            // halves into packed record: k at +0, v at +128
            __half* dst = g_kvp + (size_t)gr * 384 + ((which == 1) ? 0 : 128);
            *((__half2*)(dst + tx * 4))     = __floats2half2_rn(acc[i][0], acc[i][1]);
            *((__half2*)(dst + tx * 4 + 2)) = __floats2half2_rn(acc[i][2], acc[i][3]);
            *((__half2*)(dst + 64 + tx * 4))     = __floats2half2_rn(acc[i][4], acc[i][5]);
            *((__half2*)(dst + 64 + tx * 4 + 2)) = __floats2half2_rn(acc[i][6], acc[i][7]);
        }
    }

    if (which == 2) {
        // stage fp32 v tile into smem (reuse Xs region) for the head transpose
        float* vsm = sm;          // 64 x 132
        __syncthreads();          // everyone done with Xs/Ws
#pragma unroll
        for (int i = 0; i < 4; i++) {
            int row = ty * 4 + i;
            vsm[row * 132 + tx * 4 + 0] = acc[i][0];
            vsm[row * 132 + tx * 4 + 1] = acc[i][1];
            vsm[row * 132 + tx * 4 + 2] = acc[i][2];
            vsm[row * 132 + tx * 4 + 3] = acc[i][3];
            vsm[row * 132 + 64 + tx * 4 + 0] = acc[i][4];
            vsm[row * 132 + 64 + tx * 4 + 1] = acc[i][5];
            vsm[row * 132 + 64 + tx * 4 + 2] = acc[i][6];
            vsm[row * 132 + 64 + tx * 4 + 3] = acc[i][7];
        }
        __syncthreads();
        // psi: thread t handles row = t>>2, cols (t&3)*32 .. +31 (pairs)
        const int row = t >> 2;
        const int grp = t & 3;
        const int gr = r0 + row;
        if (gr < NN) {
            __half* dst = g_kvp + (size_t)gr * 384 + 256;
            const float* vrow = vsm + row * 132;
#pragma unroll
            for (int j = 0; j < 32; j += 2) {
                const int c = grp * 32 + j;          // even -> c, c+1 share a head
                const int head = c >> 4;
                const int d0 = c & 15, d1 = (c + 1) & 15;
                float s0 = bps[d0], s1 = bps[d1];
                const float* vh = vrow + head * 16;
#pragma unroll
                for (int d = 0; d < 16; d++) {
                    s0 = fmaf(vh[d], Wp[d * 16 + d0], s0);
                    s1 = fmaf(vh[d], Wp[d * 16 + d1], s1);
                }
                *((__half2*)(dst + c)) = __floats2half2_rn(tanhf(s0), tanhf(s1));
            }
        }
    }
}

// ---------------- fused edge pass: one warp per destination row, 4-deep unroll ---
// Packed half record per source node: k|v|psi (768B). Per 4-edge batch the warp
// issues 12 independent 8B loads (MLP=12) before any math, hiding L2 latency.
// Accumulation pairing matches the old 2-way loop -> numerics preserved.
__global__ void __launch_bounds__(256) edge_kernel() {
    const int r = (blockIdx.x << 3) + (threadIdx.x >> 5);
    const int lane = threadIdx.x & 31;
    const int s0 = g_off[r];
    const int s1 = g_off[r + 1];
    const float4 qv = *((const float4*)(g_q + (size_t)r * 128) + lane);
    float4 alp = make_float4(0.f, 0.f, 0.f, 0.f);
    float4 abp = make_float4(0.f, 0.f, 0.f, 0.f);
    float ssum = 0.f;
    const uint2* kvp = (const uint2*)g_kvp;   // 96 uint2 (=384 halves) per node

    int e = s0;
    for (; e + 4 <= s1; e += 4) {
        const int c0 = g_scol[e];
        const int c1 = g_scol[e + 1];
        const int c2 = g_scol[e + 2];
        const int c3 = g_scol[e + 3];
        const uint2* b0 = kvp + c0 * 96 + lane;
        const uint2* b1 = kvp + c1 * 96 + lane;
        const uint2* b2 = kvp + c2 * 96 + lane;
        const uint2* b3 = kvp + c3 * 96 + lane;
        const uint2 k0 = b0[0],  k1 = b1[0],  k2 = b2[0],  k3 = b3[0];
        const uint2 v0 = b0[32], v1 = b1[32], v2 = b2[32], v3 = b3[32];
        const uint2 p0 = b0[64], p1 = b1[64], p2 = b2[64], p3 = b3[64];

        float2 ka, kb;
        ka = __half22float2(*(const __half2*)&k0.x);
        kb = __half22float2(*(const __half2*)&k0.y);
        float d0 = fmaf(qv.x, ka.x, fmaf(qv.y, ka.y, fmaf(qv.z, kb.x, qv.w * kb.y)));
        ka = __half22float2(*(const __half2*)&k1.x);
        kb = __half22float2(*(const __half2*)&k1.y);
        float d1 = fmaf(qv.x, ka.x, fmaf(qv.y, ka.y, fmaf(qv.z, kb.x, qv.w * kb.y)));
        ka = __half22float2(*(const __half2*)&k2.x);
        kb = __half22float2(*(const __half2*)&k2.y);
        float d2 = fmaf(qv.x, ka.x, fmaf(qv.y, ka.y, fmaf(qv.z, kb.x, qv.w * kb.y)));
        ka = __half22float2(*(const __half2*)&k3.x);
        kb = __half22float2(*(const __half2*)&k3.y);
        float d3 = fmaf(qv.x, ka.x, fmaf(qv.y, ka.y, fmaf(qv.z, kb.x, qv.w * kb.y)));
        d0 += __shfl_xor_sync(0xffffffffu, d0, 1);
        d1 += __shfl_xor_sync(0xffffffffu, d1, 1);
        d2 += __shfl_xor_sync(0xffffffffu, d2, 1);
        d3 += __shfl_xor_sync(0xffffffffu, d3, 1);
        d0 += __shfl_xor_sync(0xffffffffu, d0, 2);
        d1 += __shfl_xor_sync(0xffffffffu, d1, 2);
        d2 += __shfl_xor_sync(0xffffffffu, d2, 2);
        d3 += __shfl_xor_sync(0xffffffffu, d3, 2);
        const float w0 = __expf(d0 * 0.25f);
        const float w1 = __expf(d1 * 0.25f);
        const float w2 = __expf(d2 * 0.25f);
        const float w3 = __expf(d3 * 0.25f);
        ssum += w0 + w1;
        ssum += w2 + w3;

        float2 va, vb;
        va = __half22float2(*(const __half2*)&v0.x);
        vb = __half22float2(*(const __half2*)&v0.y);
        alp.x = fmaf(w0, va.x, alp.x); alp.y = fmaf(w0, va.y, alp.y);
        alp.z = fmaf(w0, vb.x, alp.z); alp.w = fmaf(w0, vb.y, alp.w);
        va = __half22float2(*(const __half2*)&v1.x);
        vb = __half22float2(*(const __half2*)&v1.y);
        alp.x = fmaf(w1, va.x, alp.x); alp.y = fmaf(w1, va.y, alp.y);
        alp.z = fmaf(w1, vb.x, alp.z); alp.w = fmaf(w1, vb.y, alp.w);
        va = __half22float2(*(const __half2*)&v2.x);
        vb = __half22float2(*(const __half2*)&v2.y);
        alp.x = fmaf(w2, va.x, alp.x); alp.y = fmaf(w2, va.y, alp.y);
        alp.z = fmaf(w2, vb.x, alp.z); alp.w = fmaf(w2, vb.y, alp.w);
        va = __half22float2(*(const __half2*)&v3.x);
        vb = __half22float2(*(const __half2*)&v3.y);
        alp.x = fmaf(w3, va.x, alp.x); alp.y = fmaf(w3, va.y, alp.y);
        alp.z = fmaf(w3, vb.x, alp.z); alp.w = fmaf(w3, vb.y, alp.w);

        float2 pa, pb;
        pa = __half22float2(*(const __half2*)&p0.x);
        pb = __half22float2(*(const __half2*)&p0.y);
        abp.x = fmaf(w0, pa.x, abp.x); abp.y = fmaf(w0, pa.y, abp.y);
        abp.z = fmaf(w0, pb.x, abp.z); abp.w = fmaf(w0, pb.y, abp.w);
        pa = __half22float2(*(const __half2*)&p1.x);
        pb = __half22float2(*(const __half2*)&p1.y);
        abp.x = fmaf(w1, pa.x, abp.x); abp.y = fmaf(w1, pa.y, abp.y);
        abp.z = fmaf(w1, pb.x, abp.z); abp.w = fmaf(w1, pb.y, abp.w);
        pa = __half22float2(*(const __half2*)&p2.x);
        pb = __half22float2(*(const __half2*)&p2.y);
        abp.x = fmaf(w2, pa.x, abp.x); abp.y = fmaf(w2, pa.y, abp.y);
        abp.z = fmaf(w2, pb.x, abp.z); abp.w = fmaf(w2, pb.y, abp.w);
        pa = __half22float2(*(const __half2*)&p3.x);
        pb = __half22float2(*(const __half2*)&p3.y);
        abp.x = fmaf(w3, pa.x, abp.x); abp.y = fmaf(w3, pa.y, abp.y);
        abp.z = fmaf(w3, pb.x, abp.z); abp.w = fmaf(w3, pb.y, abp.w);
    }
    for (; e < s1; e++) {
        const int c0 = g_scol[e];
        const uint2* b0 = kvp + c0 * 96 + lane;
        const uint2 k0 = b0[0];
        const uint2 v0 = b0[32];
        const uint2 p0 = b0[64];
        float2 k0a = __half22float2(*(const __half2*)&k0.x);
        float2 k0b = __half22float2(*(const __half2*)&k0.y);
        float d0 = fmaf(qv.x, k0a.x, fmaf(qv.y, k0a.y, fmaf(qv.z, k0b.x, qv.w * k0b.y)));
        d0 += __shfl_xor_sync(0xffffffffu, d0, 1);
        d0 += __shfl_xor_sync(0xffffffffu, d0, 2);
        const float w0 = __expf(d0 * 0.25f);
        ssum += w0;
        float2 va = __half22float2(*(const __half2*)&v0.x);
        float2 vb = __half22float2(*(const __half2*)&v0.y);
        alp.x = fmaf(w0, va.x, alp.x); alp.y = fmaf(w0, va.y, alp.y);
        alp.z = fmaf(w0, vb.x, alp.z); alp.w = fmaf(w0, vb.y, alp.w);
        float2 pa = __half22float2(*(const __half2*)&p0.x);
        float2 pb = __half22float2(*(const __half2*)&p0.y);
        abp.x = fmaf(w0, pa.x, abp.x); abp.y = fmaf(w0, pa.y, abp.y);
        abp.z = fmaf(w0, pb.x, abp.z); abp.w = fmaf(w0, pb.y, abp.w);
    }
    const float inv = 1.f / (ssum + 1e-16f);
    float4 o;
    o.x = alp.x * inv; o.y = alp.y * inv; o.z = alp.z * inv; o.w = alp.w * inv;
    *((float4*)(g_hcat + (size_t)r * 256) + lane) = o;
    o.x = abp.x * inv; o.y = abp.y * inv; o.z = abp.z * inv; o.w = abp.w * inv;
    *((float4*)(g_hcat + (size_t)r * 256 + 128) + lane) = o;
}

// ---------------- output GEMM + residual + ReLU + LayerNorm ----------------
__global__ void __launch_bounds__(256) final_kernel(const float* __restrict__ X,
                                                    const float* __restrict__ Wo,
                                                    const float* __restrict__ bo,
                                                    const float* __restrict__ gamma,
                                                    const float* __restrict__ beta,
                                                    float* __restrict__ Y) {
    extern __shared__ float sm[];
    float* Ws = sm;               // [256 k][128 col]
    float* Hs = sm + 256 * 128;   // [256 k][68] transposed H tile (rows 0..63)

    const int t = threadIdx.x;
    const int r0 = blockIdx.x * 64;

    for (int i = t; i < 256 * 32; i += 256)
        ((float4*)Ws)[i] = ((const float4*)Wo)[i];
    for (int i = t; i < 64 * 64; i += 256) {
        int row = i >> 6, c4 = i & 63;
        int gr = r0 + row;
        float4 val = make_float4(0.f, 0.f, 0.f, 0.f);
        if (gr < NN) val = ((const float4*)(g_hcat + (size_t)gr * 256))[c4];
        Hs[(4 * c4 + 0) * 68 + row] = val.x;
        Hs[(4 * c4 + 1) * 68 + row] = val.y;
        Hs[(4 * c4 + 2) * 68 + row] = val.z;
        Hs[(4 * c4 + 3) * 68 + row] = val.w;
    }
    __syncthreads();

    const int tx = t & 15;
    const int ty = t >> 4;

    float acc[4][8];
    {
        float4 c0 = *((const float4*)(bo + tx * 4));
        float4 c1 = *((const float4*)(bo + 64 + tx * 4));
#pragma unroll
        for (int i = 0; i < 4; i++) {
            acc[i][0] = c0.x; acc[i][1] = c0.y; acc[i][2] = c0.z; acc[i][3] = c0.w;
            acc[i][4] = c1.x; acc[i][5] = c1.y; acc[i][6] = c1.z; acc[i][7] = c1.w;
        }
    }
#pragma unroll 4
    for (int k = 0; k < 256; k++) {
        float4 a  = *((const float4*)(Hs + k * 68 + ty * 4));
        float4 b0 = *((const float4*)(Ws + k * 128 + tx * 4));
        float4 b1 = *((const float4*)(Ws + k * 128 + 64 + tx * 4));
        float av[4] = {a.x, a.y, a.z, a.w};
        float bw[8] = {b0.x, b0.y, b0.z, b0.w, b1.x, b1.y, b1.z, b1.w};
#pragma unroll
        for (int i = 0; i < 4; i++)
#pragma unroll
            for (int j = 0; j < 8; j++)
                acc[i][j] = fmaf(av[i], bw[j], acc[i][j]);
    }

    const float4 gm0 = *((const float4*)(gamma + tx * 4));
    const float4 gm1 = *((const float4*)(gamma + 64 + tx * 4));
    const float4 bt0 = *((const float4*)(beta + tx * 4));
    const float4 bt1 = *((const float4*)(beta + 64 + tx * 4));

#pragma unroll
    for (int i = 0; i < 4; i++) {
        int gr = r0 + ty * 4 + i;
        bool ok = gr < NN;
        float4 x0 = make_float4(0.f, 0.f, 0.f, 0.f);
        float4 x1 = make_float4(0.f, 0.f, 0.f, 0.f);
        if (ok) {
            x0 = *((const float4*)(X + (size_t)gr * 128 + tx * 4));
            x1 = *((const float4*)(X + (size_t)gr * 128 + 64 + tx * 4));
        }
        float y[8];
        y[0] = x0.x + fmaxf(acc[i][0], 0.f);
        y[1] = x0.y + fmaxf(acc[i][1], 0.f);
        y[2] = x0.z + fmaxf(acc[i][2], 0.f);
        y[3] = x0.w + fmaxf(acc[i][3], 0.f);
        y[4] = x1.x + fmaxf(acc[i][4], 0.f);
        y[5] = x1.y + fmaxf(acc[i][5], 0.f);
        y[6] = x1.z + fmaxf(acc[i][6], 0.f);
        y[7] = x1.w + fmaxf(acc[i][7], 0.f);
        float ps = 0.f, pq = 0.f;
#pragma unroll
        for (int j = 0; j < 8; j++) { ps += y[j]; pq += y[j] * y[j]; }
        // reduce across the 16 lanes (same ty) that own this row
#pragma unroll
        for (int off = 1; off < 16; off <<= 1) {
            ps += __shfl_xor_sync(0xffffffffu, ps, off);
            pq += __shfl_xor_sync(0xffffffffu, pq, off);
        }
        float mu = ps * (1.f / 128.f);
        float sq = pq * (1.f / 128.f);
        float rsig = rsqrtf(sq - mu * mu + 1e-5f);
        if (ok) {
            float4 o;
            o.x = (y[0] - mu) * rsig * gm0.x + bt0.x;
            o.y = (y[1] - mu) * rsig * gm0.y + bt0.y;
            o.z = (y[2] - mu) * rsig * gm0.z + bt0.z;
            o.w = (y[3] - mu) * rsig * gm0.w + bt0.w;
            *((float4*)(Y + (size_t)gr * 128 + tx * 4)) = o;
            o.x = (y[4] - mu) * rsig * gm1.x + bt1.x;
            o.y = (y[5] - mu) * rsig * gm1.y + bt1.y;
            o.z = (y[6] - mu) * rsig * gm1.z + bt1.z;
            o.w = (y[7] - mu) * rsig * gm1.w + bt1.w;
            *((float4*)(Y + (size_t)gr * 128 + 64 + tx * 4)) = o;
        }
    }
}

// ---------------- launch ----------------
extern "C" void kernel_launch(void* const* d_in, const int* in_sizes, int n_in,
                              void* d_out, int out_size) {
    const float* x     = (const float*)d_in[0];
    const void*  ei    = d_in[1];
    const float* Wq    = (const float*)d_in[2];
    const float* bq    = (const float*)d_in[3];
    const float* Wk    = (const float*)d_in[4];
    const float* bk    = (const float*)d_in[5];
    const float* Wv    = (const float*)d_in[6];
    const float* bv    = (const float*)d_in[7];
    const float* Wpsi  = (const float*)d_in[8];
    const float* bpsi  = (const float*)d_in[9];
    const float* Wo    = (const float*)d_in[10];
    const float* bo    = (const float*)d_in[11];
    const float* gamma = (const float*)d_in[12];
    const float* beta  = (const float*)d_in[13];
    float* out = (float*)d_out;
    (void)in_sizes; (void)n_in; (void)out_size;

    const int SMEM_QKV   = (128 * 68 + 128 * 128 + 256 + 16) * 4;  // 101440 B
    const int SMEM_FINAL = (256 * 128 + 256 * 68) * 4;             // 200704 B
    (void)cudaFuncSetAttribute(gemm_qkv,     cudaFuncAttributeMaxDynamicSharedMemorySize, SMEM_QKV);
    (void)cudaFuncSetAttribute(final_kernel, cudaFuncAttributeMaxDynamicSharedMemorySize, SMEM_FINAL);

    // edge preprocessing (counting sort by destination row)
    detect_zero_kernel<<<20, 1024>>>((const int*)ei);
    decode_hist_kernel<<<EE / 1024, 1024>>>(ei);
    scan_kernel<<<1, 1024>>>();
    scatter_kernel<<<EE / 1024, 1024>>>();

    // node-level projections (fused QKV + psi via grid.y)
    gemm_qkv<<<dim3(313, 3), 256, SMEM_QKV>>>(x, Wq, bq, Wk, bk, Wv, bv, Wpsi, bpsi);

    // fused attention edge pass
    edge_kernel<<<NN / 8, 256>>>();

    // output projection + residual + ReLU + LayerNorm
    final_kernel<<<313, 256, SMEM_FINAL>>>(x, Wo, bo, gamma, beta, out);
}